// round 14
// baseline (speedup 1.0000x reference)
#include <cuda_runtime.h>
#include <cuda_fp16.h>
#include <cstdint>

#define CDIM   2048
#define EDIM   64
#define NTOT   128          // 64 route + 64 noise outputs fused in N
#define TOPK   8
#define MT     128          // tokens per CTA
#define KC     64           // K per chunk (4 ks-steps of 16)
#define NCHUNK (CDIM / KC)  // 32
#define NTHR   512          // 8 consumer warps + 8 producer warps
#define NSTAGE 3

// operand scaling to keep fp16 residuals out of subnormal range
#define XSCALE   16.0f
#define WSCALE   64.0f
#define DESCALE  (1.0f / (XSCALE * WSCALE))

// smem tile rows: 64 halves (128B) padded to 144B (conflict-free ldmatrix)
#define AROW        144
#define TILE_B      (128 * AROW)        // 18432 B per operand tile (A or B, hi or lo)
#define STAGE_B     (4 * TILE_B)        // Ahi, Alo, Bhi, Blo = 73728 B
#define SMEM_DYN    (NSTAGE * STAGE_B)  // 221184 B (reused as Ls in epilogue)
#define LS_STRIDE   129                 // 128*129*4 = 66048 B <= STAGE_B (stage 0 only)

// named barriers (id 0 = __syncthreads)
#define BAR_SYNC(id, n)   asm volatile("bar.sync %0, %1;"   :: "r"(id), "r"(n) : "memory")
#define BAR_ARRIVE(id, n) asm volatile("bar.arrive %0, %1;" :: "r"(id), "r"(n) : "memory")
#define FULL_BASE  1      // ids 1..3
#define EMPTY_BASE 4      // ids 4..6
#define CONS_BAR   7      // consumer-only barrier, count 256

static __device__ __forceinline__ uint32_t smem_u32(const void* p) {
    uint32_t a;
    asm("{ .reg .u64 t; cvta.to.shared.u64 t, %1; cvt.u32.u64 %0, t; }" : "=r"(a) : "l"(p));
    return a;
}
static __device__ __forceinline__ void ldm_x4(uint32_t& r0, uint32_t& r1, uint32_t& r2,
                                              uint32_t& r3, uint32_t addr) {
    asm volatile("ldmatrix.sync.aligned.m8n8.x4.shared.b16 {%0,%1,%2,%3}, [%4];"
                 : "=r"(r0), "=r"(r1), "=r"(r2), "=r"(r3) : "r"(addr));
}
static __device__ __forceinline__ void mma16816(float* c, const uint32_t* a,
                                                const uint32_t* b) {
    asm volatile(
        "mma.sync.aligned.m16n8k16.row.col.f32.f16.f16.f32 "
        "{%0,%1,%2,%3}, {%4,%5,%6,%7}, {%8,%9}, {%0,%1,%2,%3};"
        : "+f"(c[0]), "+f"(c[1]), "+f"(c[2]), "+f"(c[3])
        : "r"(a[0]), "r"(a[1]), "r"(a[2]), "r"(a[3]), "r"(b[0]), "r"(b[1]));
}
// Scale, split into hi/lo fp16 via packed converts (per-lane rn rounding ==
// scalar __float2half_rn path -> bitwise-identical results).
static __device__ __forceinline__ void cvt_store(char* hi, char* lo, uint32_t off,
                                                 float4 v, float scale) {
    float2 a = make_float2(v.x * scale, v.y * scale);
    float2 b = make_float2(v.z * scale, v.w * scale);
    __half2 h0 = __float22half2_rn(a);
    __half2 h1 = __float22half2_rn(b);
    float2 fa = __half22float2(h0);
    float2 fb = __half22float2(h1);
    __half2 l0 = __floats2half2_rn(a.x - fa.x, a.y - fa.y);
    __half2 l1 = __floats2half2_rn(b.x - fb.x, b.y - fb.y);
    uint2 ph = make_uint2(*(uint32_t*)&h0, *(uint32_t*)&h1);
    uint2 pl = make_uint2(*(uint32_t*)&l0, *(uint32_t*)&l1);
    *(uint2*)(hi + off) = ph;
    *(uint2*)(lo + off) = pl;
}

__global__ __launch_bounds__(NTHR, 1)
void router_mma_kernel(
    const float* __restrict__ x, const float* __restrict__ w_route,
    const float* __restrict__ w_noise, const float* __restrict__ noise,
    float* __restrict__ out_router, float* __restrict__ out_indices, int write_indices)
{
    extern __shared__ __align__(16) char smem[];
    __shared__ float s_max[MT];
    __shared__ float s_inv[MT];
    __shared__ unsigned long long s_msk[MT];

    const uint32_t sb = smem_u32(smem);
    const int tid = threadIdx.x;
    const int wid = tid >> 5, lane = tid & 31;
    const int tokBase = blockIdx.x * MT;
    const bool is_consumer = (wid < 8);

    if (!is_consumer) {
        // ================= PRODUCER (warps 8..15, 256 threads) =================
        const int ptid = tid - 256;
        // warm L2 for the epilogue's noise loads (32 KB per CTA, one line/thread)
        asm volatile("prefetch.global.L2 [%0];"
                     :: "l"(noise + (size_t)tokBase * EDIM + ptid * 32) : "memory");
        for (int c = 0; c < NCHUNK; ++c) {
            const int s = c % NSTAGE;
            if (c >= NSTAGE) BAR_SYNC(EMPTY_BASE + s, NTHR);
            char* stg = smem + s * STAGE_B;
            const int kbase = c * KC;
#pragma unroll
            for (int r = 0; r < 2; ++r) {
                float4 xv[4], wv[4];
#pragma unroll
                for (int i = 0; i < 4; ++i) {
                    const int idx = ptid + 256 * (r * 4 + i);
                    const int row = idx >> 4, q = idx & 15;
                    xv[i] = *(const float4*)(x + (size_t)(tokBase + row) * CDIM
                                             + kbase + q * 4);
                    const float* wsrc = (row < EDIM)
                        ? (w_route + (size_t)row * CDIM)
                        : (w_noise + (size_t)(row - EDIM) * CDIM);
                    wv[i] = *(const float4*)(wsrc + kbase + q * 4);
                }
#pragma unroll
                for (int i = 0; i < 4; ++i) {
                    const int idx = ptid + 256 * (r * 4 + i);
                    const int row = idx >> 4, q = idx & 15;
                    const uint32_t off = (uint32_t)row * AROW + q * 8;
                    cvt_store(stg, stg + TILE_B, off, xv[i], XSCALE);
                    cvt_store(stg + 2 * TILE_B, stg + 3 * TILE_B, off, wv[i], WSCALE);
                }
            }
            BAR_ARRIVE(FULL_BASE + s, NTHR);
        }
    } else {
        // ================= CONSUMER (warps 0..7) =================
        const int wr_ = wid >> 1;        // token rows [32*wr_, +32)
        const int wc_ = wid & 1;         // output cols [64*wc_, +64)
        const int j = lane >> 3, rr = lane & 7;
        const int a_off0 = (32 * wr_ + (j & 1) * 8 + rr) * AROW + (j >> 1) * 16;
        const int b_off0 = (64 * wc_ + (j >> 1) * 8 + rr) * AROW + (j & 1) * 16;

        float acc[2][8][4];
#pragma unroll
        for (int mt = 0; mt < 2; ++mt)
#pragma unroll
            for (int nt = 0; nt < 8; ++nt)
#pragma unroll
                for (int k = 0; k < 4; ++k) acc[mt][nt][k] = 0.0f;

        for (int c = 0; c < NCHUNK; ++c) {
            const int s = c % NSTAGE;
            BAR_SYNC(FULL_BASE + s, NTHR);
            const uint32_t ah_b = sb + s * STAGE_B;
            const uint32_t al_b = ah_b + TILE_B;
            const uint32_t bh_b = ah_b + 2 * TILE_B;
            const uint32_t bl_b = ah_b + 3 * TILE_B;
#pragma unroll
            for (int ks = 0; ks < 4; ++ks) {
                uint32_t ahi[2][4], alo[2][4];
#pragma unroll
                for (int mt = 0; mt < 2; ++mt) {
                    const uint32_t ao = a_off0 + mt * (16 * AROW) + ks * 32;
                    ldm_x4(ahi[mt][0], ahi[mt][1], ahi[mt][2], ahi[mt][3], ah_b + ao);
                    ldm_x4(alo[mt][0], alo[mt][1], alo[mt][2], alo[mt][3], al_b + ao);
                }
#pragma unroll
                for (int nh = 0; nh < 2; ++nh) {
                    uint32_t bhiF[4][2], bloF[4][2];
                    const uint32_t bbase = b_off0 + nh * (32 * AROW) + ks * 32;
#pragma unroll
                    for (int p = 0; p < 2; ++p) {
                        ldm_x4(bhiF[2 * p][0], bhiF[2 * p][1], bhiF[2 * p + 1][0],
                               bhiF[2 * p + 1][1], bh_b + bbase + p * (16 * AROW));
                        ldm_x4(bloF[2 * p][0], bloF[2 * p][1], bloF[2 * p + 1][0],
                               bloF[2 * p + 1][1], bl_b + bbase + p * (16 * AROW));
                    }
                    // per-acc order hihi->hilo->lohi (bitwise-stable vs R11)
#pragma unroll
                    for (int mt = 0; mt < 2; ++mt)
#pragma unroll
                        for (int n4 = 0; n4 < 4; ++n4)
                            mma16816(acc[mt][nh * 4 + n4], ahi[mt], bhiF[n4]);
#pragma unroll
                    for (int mt = 0; mt < 2; ++mt)
#pragma unroll
                        for (int n4 = 0; n4 < 4; ++n4)
                            mma16816(acc[mt][nh * 4 + n4], ahi[mt], bloF[n4]);
#pragma unroll
                    for (int mt = 0; mt < 2; ++mt)
#pragma unroll
                        for (int n4 = 0; n4 < 4; ++n4)
                            mma16816(acc[mt][nh * 4 + n4], alo[mt], bhiF[n4]);
                }
            }
            BAR_ARRIVE(EMPTY_BASE + s, NTHR);
        }

        // all consumer warps must be past their stage-0 reads (chunk 30) before
        // the Ls writeback below overwrites stage 0
        BAR_SYNC(CONS_BAR, 256);

        // accumulators -> Ls[token][output] (stage-0 region, descaled)
        float* Ls = (float*)smem;
        const int r0 = 32 * wr_ + (lane >> 2);
        const int c0 = 64 * wc_ + 2 * (lane & 3);
#pragma unroll
        for (int mt = 0; mt < 2; ++mt)
#pragma unroll
            for (int nt = 0; nt < 8; ++nt) {
                const int row = r0 + 16 * mt;
                const int col = c0 + 8 * nt;
                Ls[row * LS_STRIDE + col]           = acc[mt][nt][0] * DESCALE;
                Ls[row * LS_STRIDE + col + 1]       = acc[mt][nt][1] * DESCALE;
                Ls[(row + 8) * LS_STRIDE + col]     = acc[mt][nt][2] * DESCALE;
                Ls[(row + 8) * LS_STRIDE + col + 1] = acc[mt][nt][3] * DESCALE;
            }
    }
    __syncthreads();

    // --- noisy = logit + noise * softplus(noise_logit) ---
    float* Ls = (float*)smem;
    for (int i = tid; i < MT * EDIM; i += NTHR) {
        const int t = i >> 6, e = i & 63;
        float l  = Ls[t * LS_STRIDE + e];
        float nl = Ls[t * LS_STRIDE + EDIM + e];
        float nz = noise[(size_t)(tokBase + t) * EDIM + e];
        float sp = fmaxf(nl, 0.0f) + log1pf(expf(-fabsf(nl)));
        Ls[t * LS_STRIDE + e] = fmaf(nz, sp, l);
    }
    __syncthreads();

    // --- per-token top-8 (stable: ties keep lower index) ---
    if (tid < MT) {
        const float* row = Ls + tid * LS_STRIDE;
        const float NEG_INF = __int_as_float(0xff800000);
        float best[TOPK]; int bidx[TOPK];
#pragma unroll
        for (int i = 0; i < TOPK; ++i) { best[i] = NEG_INF; bidx[i] = -1; }
        for (int e = 0; e < EDIM; ++e) {
            float v = row[e];
            if (v > best[TOPK - 1]) {
                best[TOPK - 1] = v; bidx[TOPK - 1] = e;
#pragma unroll
                for (int jj = TOPK - 1; jj > 0; --jj) {
                    if (best[jj] > best[jj - 1]) {
                        float tv = best[jj]; best[jj] = best[jj - 1]; best[jj - 1] = tv;
                        int ti = bidx[jj]; bidx[jj] = bidx[jj - 1]; bidx[jj - 1] = ti;
                    }
                }
            }
        }
        float mx = best[0], ssum = 0.0f;
        unsigned long long mask = 0ULL;
#pragma unroll
        for (int i = 0; i < TOPK; ++i) { ssum += expf(best[i] - mx); mask |= 1ULL << bidx[i]; }
        s_max[tid] = mx;
        s_inv[tid] = 1.0f / ssum;
        s_msk[tid] = mask;
        if (write_indices) {
            float* oi = out_indices + (size_t)(tokBase + tid) * TOPK;
#pragma unroll
            for (int i = 0; i < TOPK; ++i) oi[i] = (float)bidx[i];
        }
    }
    __syncthreads();

    // --- sparse softmax write (coalesced) ---
    for (int i = tid; i < MT * EDIM; i += NTHR) {
        const int t = i >> 6, e = i & 63;
        float r = 0.0f;
        if ((s_msk[t] >> e) & 1ULL)
            r = expf(Ls[t * LS_STRIDE + e] - s_max[t]) * s_inv[t];
        out_router[(size_t)(tokBase + t) * EDIM + e] = r;
    }
}

extern "C" void kernel_launch(void* const* d_in, const int* in_sizes, int n_in,
                              void* d_out, int out_size) {
    const float* x  = (const float*)d_in[0];   // (4,4096,2048)
    const float* wr = (const float*)d_in[1];   // (64,2048)
    const float* wn = (const float*)d_in[2];   // (64,2048)
    const float* nz = (const float*)d_in[3];   // (4,4096,64)
    float* out = (float*)d_out;

    const int M = in_sizes[0] / CDIM;          // 16384 tokens
    const int write_idx = (out_size >= M * EDIM + M * TOPK) ? 1 : 0;
    float* out_idx = out + (size_t)M * EDIM;

    cudaFuncSetAttribute(router_mma_kernel,
                         cudaFuncAttributeMaxDynamicSharedMemorySize, SMEM_DYN);
    router_mma_kernel<<<M / MT, NTHR, SMEM_DYN>>>(x, wr, wn, nz, out, out_idx, write_idx);
}

// round 15
// speedup vs baseline: 1.2620x; 1.2620x over previous
#include <cuda_runtime.h>
#include <cuda_fp16.h>
#include <cstdint>

#define CDIM   2048
#define EDIM   64
#define NTOT   128          // 64 route + 64 noise outputs fused in N
#define TOPK   8
#define MT     128          // tokens per CTA
#define KC     64           // K per chunk (4 ks-steps of 16)
#define NCHUNK (CDIM / KC)  // 32
#define NTHR   512          // 8 consumer warps + 8 producer warps

// operand scaling to keep fp16 residuals out of subnormal range
#define XSCALE   16.0f
#define WSCALE   64.0f
#define DESCALE  (1.0f / (XSCALE * WSCALE))

// smem tile rows: 64 halves (128B) padded to 144B (conflict-free ldmatrix)
#define AROW        144
#define TILE_B      (128 * AROW)        // 18432 B per operand tile (A or B, hi or lo)
#define STAGE_B     (4 * TILE_B)        // Ahi, Alo, Bhi, Blo = 73728 B
#define SMEM_DYN    (2 * STAGE_B)       // 147456 B (L1D keeps ~84 KB carveout)
#define LS_STRIDE   129                 // 128*129*4 = 66048 B <= STAGE_B (stage 0)

// named barriers (id 0 = __syncthreads)
#define BAR_SYNC(id)   asm volatile("bar.sync %0, %1;"   :: "r"(id), "r"(NTHR) : "memory")
#define BAR_ARRIVE(id) asm volatile("bar.arrive %0, %1;" :: "r"(id), "r"(NTHR) : "memory")
#define FULL0 1
#define FULL1 2
#define EMPTY0 3
#define EMPTY1 4

// W hi/lo fp16, pre-laid-out per chunk in the exact swizzled smem tile format:
// byte offset within chunk tile = row*AROW + ((k%64)/4)*8 + (k%4)*2
__device__ __align__(16) char Whi_g[NCHUNK * 128 * AROW];
__device__ __align__(16) char Wlo_g[NCHUNK * 128 * AROW];

static __device__ __forceinline__ uint32_t smem_u32(const void* p) {
    uint32_t a;
    asm("{ .reg .u64 t; cvta.to.shared.u64 t, %1; cvt.u32.u64 %0, t; }" : "=r"(a) : "l"(p));
    return a;
}
static __device__ __forceinline__ void cp_async16(uint32_t dst, const void* src) {
    asm volatile("cp.async.cg.shared.global [%0], [%1], 16;"
                 :: "r"(dst), "l"(src) : "memory");
}
static __device__ __forceinline__ void ldm_x4(uint32_t& r0, uint32_t& r1, uint32_t& r2,
                                              uint32_t& r3, uint32_t addr) {
    asm volatile("ldmatrix.sync.aligned.m8n8.x4.shared.b16 {%0,%1,%2,%3}, [%4];"
                 : "=r"(r0), "=r"(r1), "=r"(r2), "=r"(r3) : "r"(addr));
}
static __device__ __forceinline__ void mma16816(float* c, const uint32_t* a,
                                                const uint32_t* b) {
    asm volatile(
        "mma.sync.aligned.m16n8k16.row.col.f32.f16.f16.f32 "
        "{%0,%1,%2,%3}, {%4,%5,%6,%7}, {%8,%9}, {%0,%1,%2,%3};"
        : "+f"(c[0]), "+f"(c[1]), "+f"(c[2]), "+f"(c[3])
        : "r"(a[0]), "r"(a[1]), "r"(a[2]), "r"(a[3]), "r"(b[0]), "r"(b[1]));
}
// Scale, split into hi/lo fp16 via packed converts (per-lane rn rounding).
static __device__ __forceinline__ void split4(float4 v, float scale,
                                              uint2& ph, uint2& pl) {
    float2 a = make_float2(v.x * scale, v.y * scale);
    float2 b = make_float2(v.z * scale, v.w * scale);
    __half2 h0 = __float22half2_rn(a);
    __half2 h1 = __float22half2_rn(b);
    float2 fa = __half22float2(h0);
    float2 fb = __half22float2(h1);
    __half2 l0 = __floats2half2_rn(a.x - fa.x, a.y - fa.y);
    __half2 l1 = __floats2half2_rn(b.x - fb.x, b.y - fb.y);
    ph = make_uint2(*(uint32_t*)&h0, *(uint32_t*)&h1);
    pl = make_uint2(*(uint32_t*)&l0, *(uint32_t*)&l1);
}
static __device__ __forceinline__ void cvt_store(char* hi, char* lo, uint32_t off,
                                                 float4 v, float scale) {
    uint2 ph, pl;
    split4(v, scale, ph, pl);
    *(uint2*)(hi + off) = ph;
    *(uint2*)(lo + off) = pl;
}

// ---- prep: split W (route||noise) into per-chunk swizzled hi/lo tiles ----
__global__ void prep_w_kernel(const float* __restrict__ wr, const float* __restrict__ wn) {
    const int e = blockIdx.x * blockDim.x + threadIdx.x;   // one float4 per thread
    if (e >= NTOT * (CDIM / 4)) return;
    const int o = e >> 9;              // output row 0..127
    const int k = (e & 511) * 4;       // col 0..2044
    const float* wsrc = (o < EDIM) ? (wr + (size_t)o * CDIM)
                                   : (wn + (size_t)(o - EDIM) * CDIM);
    float4 v = *(const float4*)(wsrc + k);
    uint2 ph, pl;
    split4(v, WSCALE, ph, pl);
    const uint32_t off = (uint32_t)(k >> 6) * (128 * AROW) + o * AROW
                       + ((k & 63) >> 2) * 8;
    *(uint2*)(Whi_g + off) = ph;
    *(uint2*)(Wlo_g + off) = pl;
}

__global__ __launch_bounds__(NTHR, 1)
void router_mma_kernel(
    const float* __restrict__ x, const float* __restrict__ noise,
    float* __restrict__ out_router, float* __restrict__ out_indices, int write_indices)
{
    extern __shared__ __align__(16) char smem[];
    __shared__ float s_max[MT];
    __shared__ float s_inv[MT];
    __shared__ unsigned long long s_msk[MT];

    const uint32_t sb = smem_u32(smem);
    const int tid = threadIdx.x;
    const int wid = tid >> 5, lane = tid & 31;
    const int tokBase = blockIdx.x * MT;
    const bool is_consumer = (wid < 8);

    if (!is_consumer) {
        // ================= PRODUCER (warps 8..15, 256 threads) =================
        const int ptid = tid - 256;
        // warm L2 for the epilogue's noise loads (32 KB per CTA)
        asm volatile("prefetch.global.L2 [%0];"
                     :: "l"(noise + (size_t)tokBase * EDIM + ptid * 32) : "memory");
        for (int c = 0; c < NCHUNK; ++c) {
            const int s = c & 1;
            if (c >= 2) BAR_SYNC(EMPTY0 + s);
            char* stg = smem + s * STAGE_B;
            const uint32_t stg32 = sb + s * STAGE_B;
            const int kbase = c * KC;

            // B tiles: 9 x 16B cp.async per thread from pre-swizzled globals
            const char* whi = Whi_g + (size_t)c * (128 * AROW);
            const char* wlo = Wlo_g + (size_t)c * (128 * AROW);
#pragma unroll
            for (int i = 0; i < 9; ++i) {
                const int idx = ptid + 256 * i;            // 0..2303
                if (idx < 1152)
                    cp_async16(stg32 + 2 * TILE_B + idx * 16, whi + idx * 16);
                else
                    cp_async16(stg32 + 3 * TILE_B + (idx - 1152) * 16,
                               wlo + (idx - 1152) * 16);
            }

            // A tile: load + split + store (8 float4 per thread)
            float4 xv[8];
#pragma unroll
            for (int i = 0; i < 8; ++i) {
                const int idx = ptid + 256 * i;
                const int row = idx >> 4, q = idx & 15;
                xv[i] = *(const float4*)(x + (size_t)(tokBase + row) * CDIM
                                         + kbase + q * 4);
            }
#pragma unroll
            for (int i = 0; i < 8; ++i) {
                const int idx = ptid + 256 * i;
                const int row = idx >> 4, q = idx & 15;
                cvt_store(stg, stg + TILE_B, (uint32_t)row * AROW + q * 8,
                          xv[i], XSCALE);
            }

            asm volatile("cp.async.commit_group;" ::: "memory");
            asm volatile("cp.async.wait_group 0;" ::: "memory");
            BAR_ARRIVE(FULL0 + s);
        }
    } else {
        // ================= CONSUMER (warps 0..7) =================
        const int wr_ = wid >> 1;        // token rows [32*wr_, +32)
        const int wc_ = wid & 1;         // output cols [64*wc_, +64)
        const int j = lane >> 3, rr = lane & 7;
        const int a_off0 = (32 * wr_ + (j & 1) * 8 + rr) * AROW + (j >> 1) * 16;
        const int b_off0 = (64 * wc_ + (j >> 1) * 8 + rr) * AROW + (j & 1) * 16;

        float acc[2][8][4];
#pragma unroll
        for (int mt = 0; mt < 2; ++mt)
#pragma unroll
            for (int nt = 0; nt < 8; ++nt)
#pragma unroll
                for (int k = 0; k < 4; ++k) acc[mt][nt][k] = 0.0f;

        for (int c = 0; c < NCHUNK; ++c) {
            const int s = c & 1;
            BAR_SYNC(FULL0 + s);
            const uint32_t ah_b = sb + s * STAGE_B;
            const uint32_t al_b = ah_b + TILE_B;
            const uint32_t bh_b = ah_b + 2 * TILE_B;
            const uint32_t bl_b = ah_b + 3 * TILE_B;
#pragma unroll
            for (int ks = 0; ks < 4; ++ks) {
                uint32_t ahi[2][4], alo[2][4];
#pragma unroll
                for (int mt = 0; mt < 2; ++mt) {
                    const uint32_t ao = a_off0 + mt * (16 * AROW) + ks * 32;
                    ldm_x4(ahi[mt][0], ahi[mt][1], ahi[mt][2], ahi[mt][3], ah_b + ao);
                    ldm_x4(alo[mt][0], alo[mt][1], alo[mt][2], alo[mt][3], al_b + ao);
                }
#pragma unroll
                for (int nh = 0; nh < 2; ++nh) {
                    uint32_t bhiF[4][2], bloF[4][2];
                    const uint32_t bbase = b_off0 + nh * (32 * AROW) + ks * 32;
#pragma unroll
                    for (int p = 0; p < 2; ++p) {
                        ldm_x4(bhiF[2 * p][0], bhiF[2 * p][1], bhiF[2 * p + 1][0],
                               bhiF[2 * p + 1][1], bh_b + bbase + p * (16 * AROW));
                        ldm_x4(bloF[2 * p][0], bloF[2 * p][1], bloF[2 * p + 1][0],
                               bloF[2 * p + 1][1], bl_b + bbase + p * (16 * AROW));
                    }
                    // per-acc order hihi->hilo->lohi (bitwise-stable vs R11)
#pragma unroll
                    for (int mt = 0; mt < 2; ++mt)
#pragma unroll
                        for (int n4 = 0; n4 < 4; ++n4)
                            mma16816(acc[mt][nh * 4 + n4], ahi[mt], bhiF[n4]);
#pragma unroll
                    for (int mt = 0; mt < 2; ++mt)
#pragma unroll
                        for (int n4 = 0; n4 < 4; ++n4)
                            mma16816(acc[mt][nh * 4 + n4], ahi[mt], bloF[n4]);
#pragma unroll
                    for (int mt = 0; mt < 2; ++mt)
#pragma unroll
                        for (int n4 = 0; n4 < 4; ++n4)
                            mma16816(acc[mt][nh * 4 + n4], alo[mt], bhiF[n4]);
                }
            }
            BAR_ARRIVE(EMPTY0 + s);
        }

        // accumulators -> Ls[token][output] (stage-0 region; all consumers are
        // past chunk 30's reads of stage 0; chunk 31 reads stage 1 only)
        float* Ls = (float*)smem;
        const int r0 = 32 * wr_ + (lane >> 2);
        const int c0 = 64 * wc_ + 2 * (lane & 3);
#pragma unroll
        for (int mt = 0; mt < 2; ++mt)
#pragma unroll
            for (int nt = 0; nt < 8; ++nt) {
                const int row = r0 + 16 * mt;
                const int col = c0 + 8 * nt;
                Ls[row * LS_STRIDE + col]           = acc[mt][nt][0] * DESCALE;
                Ls[row * LS_STRIDE + col + 1]       = acc[mt][nt][1] * DESCALE;
                Ls[(row + 8) * LS_STRIDE + col]     = acc[mt][nt][2] * DESCALE;
                Ls[(row + 8) * LS_STRIDE + col + 1] = acc[mt][nt][3] * DESCALE;
            }
    }
    __syncthreads();

    // --- noisy = logit + noise * softplus(noise_logit) ---
    float* Ls = (float*)smem;
    for (int i = tid; i < MT * EDIM; i += NTHR) {
        const int t = i >> 6, e = i & 63;
        float l  = Ls[t * LS_STRIDE + e];
        float nl = Ls[t * LS_STRIDE + EDIM + e];
        float nz = noise[(size_t)(tokBase + t) * EDIM + e];
        float sp = fmaxf(nl, 0.0f) + log1pf(expf(-fabsf(nl)));
        Ls[t * LS_STRIDE + e] = fmaf(nz, sp, l);
    }
    __syncthreads();

    // --- per-token top-8 (stable: ties keep lower index) ---
    if (tid < MT) {
        const float* row = Ls + tid * LS_STRIDE;
        const float NEG_INF = __int_as_float(0xff800000);
        float best[TOPK]; int bidx[TOPK];
#pragma unroll
        for (int i = 0; i < TOPK; ++i) { best[i] = NEG_INF; bidx[i] = -1; }
        for (int e = 0; e < EDIM; ++e) {
            float v = row[e];
            if (v > best[TOPK - 1]) {
                best[TOPK - 1] = v; bidx[TOPK - 1] = e;
#pragma unroll
                for (int jj = TOPK - 1; jj > 0; --jj) {
                    if (best[jj] > best[jj - 1]) {
                        float tv = best[jj]; best[jj] = best[jj - 1]; best[jj - 1] = tv;
                        int ti = bidx[jj]; bidx[jj] = bidx[jj - 1]; bidx[jj - 1] = ti;
                    }
                }
            }
        }
        float mx = best[0], ssum = 0.0f;
        unsigned long long mask = 0ULL;
#pragma unroll
        for (int i = 0; i < TOPK; ++i) { ssum += expf(best[i] - mx); mask |= 1ULL << bidx[i]; }
        s_max[tid] = mx;
        s_inv[tid] = 1.0f / ssum;
        s_msk[tid] = mask;
        if (write_indices) {
            float* oi = out_indices + (size_t)(tokBase + tid) * TOPK;
#pragma unroll
            for (int i = 0; i < TOPK; ++i) oi[i] = (float)bidx[i];
        }
    }
    __syncthreads();

    // --- sparse softmax write (coalesced) ---
    for (int i = tid; i < MT * EDIM; i += NTHR) {
        const int t = i >> 6, e = i & 63;
        float r = 0.0f;
        if ((s_msk[t] >> e) & 1ULL)
            r = expf(Ls[t * LS_STRIDE + e] - s_max[t]) * s_inv[t];
        out_router[(size_t)(tokBase + t) * EDIM + e] = r;
    }
}

extern "C" void kernel_launch(void* const* d_in, const int* in_sizes, int n_in,
                              void* d_out, int out_size) {
    const float* x  = (const float*)d_in[0];   // (4,4096,2048)
    const float* wr = (const float*)d_in[1];   // (64,2048)
    const float* wn = (const float*)d_in[2];   // (64,2048)
    const float* nz = (const float*)d_in[3];   // (4,4096,64)
    float* out = (float*)d_out;

    const int M = in_sizes[0] / CDIM;          // 16384 tokens
    const int write_idx = (out_size >= M * EDIM + M * TOPK) ? 1 : 0;
    float* out_idx = out + (size_t)M * EDIM;

    prep_w_kernel<<<(NTOT * (CDIM / 4) + 255) / 256, 256>>>(wr, wn);
    cudaFuncSetAttribute(router_mma_kernel,
                         cudaFuncAttributeMaxDynamicSharedMemorySize, SMEM_DYN);
    router_mma_kernel<<<M / MT, NTHR, SMEM_DYN>>>(x, nz, out, out_idx, write_idx);
}